// round 5
// baseline (speedup 1.0000x reference)
#include <cuda_runtime.h>
#include <cuda_bf16.h>

// RKN scan R5: phase-1 distributed over all 512 threads (k-split logits,
// redundant obs update), register-resident tm (bf16 off-diag, fp32 diag),
// all carry partials in smem, 2 barriers/step.

#define NB   128
#define NT   128
#define NLOD 128
#define NK   16

__device__ __forceinline__ unsigned int pk(float a, float b) {
    __nv_bfloat162 t = __floats2bfloat162_rn(a, b);
    return reinterpret_cast<unsigned int&>(t);
}
// acc(f32x2) += { exact lo: p<<16 , approx hi: raw p (garbage low mantissa) } * {a,a}
__device__ __forceinline__ void pair_fma(unsigned long long& acc,
                                         unsigned int p, unsigned long long a2) {
    asm("{\n\t.reg .b32 lo;\n\t.reg .b64 v;\n\t"
        "shl.b32 lo, %1, 16;\n\t"
        "mov.b64 v, {lo, %1};\n\t"
        "fma.rn.f32x2 %0, v, %2, %0;\n\t}"
        : "+l"(acc) : "r"(p), "l"(a2));
}
__device__ __forceinline__ unsigned long long dup2(float a) {
    unsigned long long r;
    asm("mov.b64 %0, {%1, %1};" : "=l"(r) : "f"(a));
    return r;
}
__device__ __forceinline__ void unpk2(unsigned long long r, float& x, float& y) {
    asm("mov.b64 {%0, %1}, %2;" : "=f"(x), "=f"(y) : "l"(r));
}

#define BAND_ACC(d, a11, a12, a21, a22)                                       \
  {                                                                           \
    int j_ = i + (d);                                                         \
    float muj = s_mu[j_], mlj = s_ml[j_];                                     \
    float cuj = s_cu[j_], clj = s_cl[j_], csj = s_cs[j_];                     \
    nmu = fmaf((a11), muj, nmu); nmu = fmaf((a12), mlj, nmu);                 \
    nml = fmaf((a21), muj, nml); nml = fmaf((a22), mlj, nml);                 \
    ncu = fmaf((a11) * (a11), cuj, ncu);                                      \
    ncu = fmaf(2.0f * (a11) * (a12), csj, ncu);                               \
    ncu = fmaf((a12) * (a12), clj, ncu);                                      \
    ncl = fmaf((a21) * (a21), cuj, ncl);                                      \
    ncl = fmaf(2.0f * (a21) * (a22), csj, ncl);                               \
    ncl = fmaf((a22) * (a22), clj, ncl);                                      \
    ncs = fmaf((a21) * (a11), cuj, ncs);                                      \
    ncs = fmaf(fmaf((a22), (a11), (a21) * (a12)), csj, ncs);                  \
    ncs = fmaf((a22) * (a12), clj, ncs);                                      \
  }

__global__ void __launch_bounds__(512, 1)
rkn_kernel(const float* __restrict__ lobs,   // (B,T,LOD)
           const float* __restrict__ ovars,  // (B,T,LOD)
           const float* __restrict__ imean,  // (B,2*LOD)
           const float* __restrict__ icu,
           const float* __restrict__ icl,
           const float* __restrict__ ics,
           const float* __restrict__ tm11,   // (K,LOD,LOD)
           const float* __restrict__ tm12,
           const float* __restrict__ tm21,
           const float* __restrict__ tm22,
           const float* __restrict__ cw,     // (2*LOD, K)
           const float* __restrict__ cb,     // (K,)
           const float* __restrict__ tcu,
           const float* __restrict__ tcl,
           float* __restrict__ out)
{
    __shared__ float s_mu[136], s_ml[136], s_cu[136], s_cl[136], s_cs[136];
    __shared__ __align__(16) float red[64];   // red[k*4 + (warp&3)]
    __shared__ float4 p4[4 * NLOD];           // per-group partials (nmu,nml,ncu,ncl)
    __shared__ float  p1[4 * NLOD];           // per-group partial ncs

    const int b    = blockIdx.x;
    const int tid  = threadIdx.x;
    const int lane = tid & 31;
    const int warp = tid >> 5;
    const int i    = tid & 127;   // row
    const int g    = tid >> 7;    // group 0..3
    const int k0   = g * 4;       // this group's logits k-range

    // ---- prologue ----
    for (int idx = tid; idx < 136; idx += 512) {
        s_mu[idx] = 0.f; s_ml[idx] = 0.f;
        s_cu[idx] = 0.f; s_cl[idx] = 0.f; s_cs[idx] = 0.f;
    }

    const float bbl  = __ldg(cb + (lane & 15));
    const float tcur = __ldg(tcu + i);
    const float tclr = __ldg(tcl + i);

    // this group's 4 softmax-weight columns for row i
    float Wu4[4], Wl4[4];
    #pragma unroll
    for (int kk = 0; kk < 4; kk++) {
        Wu4[kk] = __ldg(cw + i * NK + k0 + kk);
        Wl4[kk] = __ldg(cw + (NLOD + i) * NK + k0 + kk);
    }

    // seed partials: group 0 slot carries initial state (tc pre-subtracted)
    if (g == 0) {
        p4[i] = make_float4(imean[(long)b * 2 * NLOD + i],
                            imean[(long)b * 2 * NLOD + NLOD + i],
                            icu[(long)b * NLOD + i] - tcur,
                            icl[(long)b * NLOD + i] - tclr);
        p1[i] = ics[(long)b * NLOD + i];
    } else {
        p4[g * NLOD + i] = make_float4(0.f, 0.f, 0.f, 0.f);
        p1[g * NLOD + i] = 0.f;
    }

    float obs_r = __ldg(lobs  + ((long)b * NT) * NLOD + i);
    float ov_r  = __ldg(ovars + ((long)b * NT) * NLOD + i);

    // group-resident tm tables
    float4 D[NK];      // g0: fp32 diagonal (k, i, i)
    uint4  R[NK];      // g1..3: packed bf16 pairs for 2 off-diagonals
    const int da = (g == 1) ? 0 : (g == 2) ? 2 : 5;
    const int db = (g == 1) ? 1 : (g == 2) ? 4 : 6;
    if (g == 0) {
        #pragma unroll
        for (int k = 0; k < NK; k++) {
            long base = ((long)k * NLOD + i) * NLOD + i;
            D[k] = make_float4(__ldg(tm11 + base), __ldg(tm12 + base),
                               __ldg(tm21 + base), __ldg(tm22 + base));
        }
    } else {
        const int ja = i - 3 + da, jb = i - 3 + db;
        const bool va = (unsigned)ja < (unsigned)NLOD;
        const bool vb = (unsigned)jb < (unsigned)NLOD;
        #pragma unroll
        for (int k = 0; k < NK; k++) {
            long base = ((long)k * NLOD + i) * NLOD;
            float a11 = 0.f, a12 = 0.f, a21 = 0.f, a22 = 0.f;
            float c11 = 0.f, c12 = 0.f, c21 = 0.f, c22 = 0.f;
            if (va) {
                a11 = __ldg(tm11 + base + ja); a12 = __ldg(tm12 + base + ja);
                a21 = __ldg(tm21 + base + ja); a22 = __ldg(tm22 + base + ja);
            }
            if (vb) {
                c11 = __ldg(tm11 + base + jb); c12 = __ldg(tm12 + base + jb);
                c21 = __ldg(tm21 + base + jb); c22 = __ldg(tm22 + base + jb);
            }
            R[k] = make_uint4(pk(a11, a12), pk(a21, a22),
                              pk(c11, c12), pk(c21, c22));
        }
    }

    float* out_pm = out;
    float* out_cu = out + (long)NB * NT * 2 * NLOD;
    float* out_cl = out_cu + (long)NB * NT * NLOD;
    float* out_cs = out_cl + (long)NB * NT * NLOD;

    __syncthreads();

    for (int t = 0; t < NT; t++) {
        // ================= phase 1 (ALL threads) =================
        // combine the 4 group partials for this row (redundant in all groups)
        float4 q0 = p4[i], q1 = p4[NLOD + i], q2 = p4[2 * NLOD + i], q3 = p4[3 * NLOD + i];
        float pmU = (q0.x + q1.x) + (q2.x + q3.x);
        float pmL = (q0.y + q1.y) + (q2.y + q3.y);
        float cU  = ((q0.z + q1.z) + (q2.z + q3.z)) + tcur;
        float cL  = ((q0.w + q1.w) + (q2.w + q3.w)) + tclr;
        float cS  = (p1[i] + p1[NLOD + i]) + (p1[2 * NLOD + i] + p1[3 * NLOD + i]);

        float denom = cU + ov_r;
        float rd    = 1.0f / denom;
        float qu    = cU * rd;
        float ql    = cS * rd;
        float res   = obs_r - pmU;
        float pu    = pmU + qu * res;
        float pl    = pmL + ql * res;
        float cf    = 1.0f - qu;
        float pcu   = cf * cU;
        float pcl   = cL - ql * cS;
        float pcs   = cf * cS;

        if (t + 1 < NT) {
            obs_r = __ldg(lobs  + ((long)b * NT + t + 1) * NLOD + i);
            ov_r  = __ldg(ovars + ((long)b * NT + t + 1) * NLOD + i);
        }

        // split the state publish and output stores across groups
        long obase = (long)b * NT + t;
        if (g == 0) {
            s_mu[3 + i] = pu;  s_cs[3 + i] = pcs;
            out_pm[obase * 2 * NLOD + i]        = pu;
            out_pm[obase * 2 * NLOD + NLOD + i] = pl;
        } else if (g == 1) {
            s_ml[3 + i] = pl;
            out_cu[obase * NLOD + i] = pcu;
        } else if (g == 2) {
            s_cu[3 + i] = pcu;
            out_cl[obase * NLOD + i] = pcl;
        } else {
            s_cl[3 + i] = pcl;
            out_cs[obase * NLOD + i] = pcs;
        }

        // logits for this group's 4 k's, reduced over 128 rows.
        // v[kk] = contribution of row i to logit k0+kk
        float v[4];
        #pragma unroll
        for (int kk = 0; kk < 4; kk++) v[kk] = fmaf(pu, Wu4[kk], pl * Wl4[kk]);
        // fold lanes l <-> l^16
        #pragma unroll
        for (int kk = 0; kk < 4; kk++) v[kk] += __shfl_xor_sync(0xffffffffu, v[kk], 16);
        // value-split round on lane bit 3 (4 values -> 2)
        #pragma unroll
        for (int kk = 0; kk < 2; kk++) {
            float a_ = v[kk], c_ = v[kk + 2];
            bool hi_ = (lane & 8) != 0;
            float keep_ = hi_ ? c_ : a_;
            float send_ = hi_ ? a_ : c_;
            v[kk] = keep_ + __shfl_xor_sync(0xffffffffu, send_, 8);
        }
        // value-split round on lane bit 2 (2 values -> 1)
        {
            float a_ = v[0], c_ = v[1];
            bool hi_ = (lane & 4) != 0;
            float keep_ = hi_ ? c_ : a_;
            float send_ = hi_ ? a_ : c_;
            v[0] = keep_ + __shfl_xor_sync(0xffffffffu, send_, 4);
        }
        // plain rounds on bits 1, 0
        v[0] += __shfl_xor_sync(0xffffffffu, v[0], 2);
        v[0] += __shfl_xor_sync(0xffffffffu, v[0], 1);
        // lane (b3,b2) holds k = k0 + 2*b3 + b2; lanes with (lane&3)==0 write
        if ((lane & 3) == 0) {
            int k = k0 + 2 * ((lane >> 3) & 1) + ((lane >> 2) & 1);
            red[k * 4 + (warp & 3)] = v[0];
        }
        __syncthreads();   // B1

        // ================= phase 2 =================
        // softmax (lane-parallel per warp)
        float aw;
        {
            const float4* red4 = reinterpret_cast<const float4*>(red);
            float4 rp = red4[lane & 15];
            float lg = bbl + ((rp.x + rp.y) + (rp.z + rp.w));
            float mx = lg;
            #pragma unroll
            for (int m = 8; m >= 1; m >>= 1)
                mx = fmaxf(mx, __shfl_xor_sync(0xffffffffu, mx, m));
            float w = __expf(lg - mx);
            float s = w;
            #pragma unroll
            for (int m = 8; m >= 1; m >>= 1)
                s += __shfl_xor_sync(0xffffffffu, s, m);
            aw = w * (1.0f / s);
        }

        float nmu = 0.f, nml = 0.f, ncu = 0.f, ncl = 0.f, ncs = 0.f;

        if (g == 0) {
            // fp32 diagonal d=3 (+ identity)
            float D11 = 0.f, D12 = 0.f, D21 = 0.f, D22 = 0.f;
            #pragma unroll
            for (int k = 0; k < NK; k++) {
                float a = __shfl_sync(0xffffffffu, aw, k);
                D11 = fmaf(a, D[k].x, D11);
                D12 = fmaf(a, D[k].y, D12);
                D21 = fmaf(a, D[k].z, D21);
                D22 = fmaf(a, D[k].w, D22);
            }
            BAND_ACC(3, D11 + 1.0f, D12, D21, D22 + 1.0f)
        } else {
            unsigned long long Pa = 0ull, Qa = 0ull, Pb = 0ull, Qb = 0ull;
            #pragma unroll
            for (int k = 0; k < NK; k++) {
                unsigned long long a2 = dup2(__shfl_sync(0xffffffffu, aw, k));
                uint4 r = R[k];
                pair_fma(Pa, r.x, a2);
                pair_fma(Qa, r.y, a2);
                pair_fma(Pb, r.z, a2);
                pair_fma(Qb, r.w, a2);
            }
            float a11, a12, a21, a22;
            unpk2(Pa, a11, a12); unpk2(Qa, a21, a22);
            BAND_ACC(da, a11, a12, a21, a22)
            unpk2(Pb, a11, a12); unpk2(Qb, a21, a22);
            BAND_ACC(db, a11, a12, a21, a22)
        }

        p4[g * NLOD + i] = make_float4(nmu, nml, ncu, ncl);
        p1[g * NLOD + i] = ncs;
        __syncthreads();   // B2
    }
}

extern "C" void kernel_launch(void* const* d_in, const int* in_sizes, int n_in,
                              void* d_out, int out_size)
{
    (void)in_sizes; (void)n_in; (void)out_size;
    const float* lobs  = (const float*)d_in[0];
    const float* ovars = (const float*)d_in[1];
    const float* imean = (const float*)d_in[2];
    const float* icu   = (const float*)d_in[3];
    const float* icl   = (const float*)d_in[4];
    const float* ics   = (const float*)d_in[5];
    const float* tm11  = (const float*)d_in[6];
    const float* tm12  = (const float*)d_in[7];
    const float* tm21  = (const float*)d_in[8];
    const float* tm22  = (const float*)d_in[9];
    const float* cw    = (const float*)d_in[10];
    const float* cb    = (const float*)d_in[11];
    const float* tcu   = (const float*)d_in[12];
    const float* tcl   = (const float*)d_in[13];
    float* out = (float*)d_out;

    rkn_kernel<<<NB, 512>>>(lobs, ovars, imean, icu, icl, ics,
                            tm11, tm12, tm21, tm22,
                            cw, cb, tcu, tcl, out);
}

// round 6
// speedup vs baseline: 1.8577x; 1.8577x over previous
#include <cuda_runtime.h>
#include <cuda_bf16.h>

// RKN scan R6: 256 threads/CTA, fully register-resident tm tables
// (bf16-packed off-diagonals, fp32 diagonal), lane-parallel softmax,
// float4 state, 2 barriers/step.

#define NB   128
#define NT   128
#define NLOD 128
#define NK   16

__device__ __forceinline__ unsigned int pk(float a, float b) {
    __nv_bfloat162 t = __floats2bfloat162_rn(a, b);
    return reinterpret_cast<unsigned int&>(t);
}
// acc(f32x2) += { lo: p<<16 (exact), hi: raw p (garbage low mantissa) } * {a,a}
__device__ __forceinline__ void pair_fma(unsigned long long& acc,
                                         unsigned int p, unsigned long long a2) {
    asm("{\n\t.reg .b32 lo;\n\t.reg .b64 v;\n\t"
        "shl.b32 lo, %1, 16;\n\t"
        "mov.b64 v, {lo, %1};\n\t"
        "fma.rn.f32x2 %0, v, %2, %0;\n\t}"
        : "+l"(acc) : "r"(p), "l"(a2));
}
__device__ __forceinline__ unsigned long long dup2(float a) {
    unsigned long long r;
    asm("mov.b64 %0, {%1, %1};" : "=l"(r) : "f"(a));
    return r;
}
__device__ __forceinline__ void unpk2(unsigned long long r, float& x, float& y) {
    asm("mov.b64 {%0, %1}, %2;" : "=f"(x), "=f"(y) : "l"(r));
}
__device__ __forceinline__ void bar256() {
    asm volatile("bar.sync 0, 256;" ::: "memory");
}

#define RED_ROUND(m)                                                          \
  _Pragma("unroll")                                                           \
  for (int k = 0; k < (m); k++) {                                             \
    float a_ = v[k], c_ = v[k + (m)];                                         \
    bool  hi_ = (lane & (m)) != 0;                                            \
    float keep_ = hi_ ? c_ : a_;                                              \
    float send_ = hi_ ? a_ : c_;                                              \
    v[k] = keep_ + __shfl_xor_sync(0xffffffffu, send_, (m));                  \
  }

// state float4 = {mu, ml, cu, cl}; pcs in separate array
#define BAND_ACC(d, a11, a12, a21, a22)                                       \
  {                                                                           \
    float4 st_ = s_st[i + (d)];                                               \
    float  csj = s_cs[i + (d)];                                               \
    float muj = st_.x, mlj = st_.y, cuj = st_.z, clj = st_.w;                 \
    nmu = fmaf((a11), muj, nmu); nmu = fmaf((a12), mlj, nmu);                 \
    nml = fmaf((a21), muj, nml); nml = fmaf((a22), mlj, nml);                 \
    ncu = fmaf((a11) * (a11), cuj, ncu);                                      \
    ncu = fmaf(2.0f * (a11) * (a12), csj, ncu);                               \
    ncu = fmaf((a12) * (a12), clj, ncu);                                      \
    ncl = fmaf((a21) * (a21), cuj, ncl);                                      \
    ncl = fmaf(2.0f * (a21) * (a22), csj, ncl);                               \
    ncl = fmaf((a22) * (a22), clj, ncl);                                      \
    ncs = fmaf((a21) * (a11), cuj, ncs);                                      \
    ncs = fmaf(fmaf((a22), (a11), (a21) * (a12)), csj, ncs);                  \
    ncs = fmaf((a22) * (a12), clj, ncs);                                      \
  }

// lane-parallel softmax: lane owns k = lane&15 (duplicated in upper half-warp)
#define SOFTMAX_AW(aw)                                                        \
  {                                                                           \
    const float4* red4_ = reinterpret_cast<const float4*>(red);               \
    float4 rp_ = red4_[lane & 15];                                            \
    float lg_ = bbl + ((rp_.x + rp_.y) + (rp_.z + rp_.w));                    \
    float mx_ = lg_;                                                          \
    _Pragma("unroll")                                                         \
    for (int m_ = 8; m_ >= 1; m_ >>= 1)                                       \
      mx_ = fmaxf(mx_, __shfl_xor_sync(0xffffffffu, mx_, m_));                \
    float w_ = __expf(lg_ - mx_);                                             \
    float s_ = w_;                                                            \
    _Pragma("unroll")                                                         \
    for (int m_ = 8; m_ >= 1; m_ >>= 1)                                       \
      s_ += __shfl_xor_sync(0xffffffffu, s_, m_);                             \
    (aw) = w_ * (1.0f / s_);                                                  \
  }

__global__ void __launch_bounds__(256, 1)
rkn_kernel(const float* __restrict__ lobs,   // (B,T,LOD)
           const float* __restrict__ ovars,  // (B,T,LOD)
           const float* __restrict__ imean,  // (B,2*LOD)
           const float* __restrict__ icu,
           const float* __restrict__ icl,
           const float* __restrict__ ics,
           const float* __restrict__ tm11,   // (K,LOD,LOD)
           const float* __restrict__ tm12,
           const float* __restrict__ tm21,
           const float* __restrict__ tm22,
           const float* __restrict__ cw,     // (2*LOD, K)
           const float* __restrict__ cb,     // (K,)
           const float* __restrict__ tcu,
           const float* __restrict__ tcl,
           float* __restrict__ out)
{
    __shared__ float4 s_st[136];              // rows -3..132: {mu,ml,cu,cl}
    __shared__ float  s_cs[136];
    __shared__ __align__(16) float red[64];   // red[k*4 + warp]
    __shared__ float4 p4h1[NLOD];             // h1 partial {nmu,nml,ncu,ncl}
    __shared__ float  p1h1[NLOD];             // h1 partial ncs

    const int b    = blockIdx.x;
    const int tid  = threadIdx.x;
    const int lane = tid & 31;
    const int warp = tid >> 5;
    const int i    = tid & 127;   // row
    const int h    = tid >> 7;    // half 0/1

    // ---- prologue (convergent) ----
    for (int idx = tid; idx < 136; idx += 256) {
        s_st[idx] = make_float4(0.f, 0.f, 0.f, 0.f);
        s_cs[idx] = 0.f;
    }
    if (h == 1) {
        p4h1[i] = make_float4(0.f, 0.f, 0.f, 0.f);
        p1h1[i] = 0.f;
    }
    const float bbl = __ldg(cb + (lane & 15));

    float* out_pm = out;
    float* out_cu = out + (long)NB * NT * 2 * NLOD;
    float* out_cl = out_cu + (long)NB * NT * NLOD;
    float* out_cs = out_cl + (long)NB * NT * NLOD;

    __syncthreads();

    if (h == 0) {
        // ================== h0: serial head + diagonals {0,1,3} ==================
        float Wu[NK], Wl[NK];
        #pragma unroll
        for (int k = 0; k < NK; k++) {
            Wu[k] = __ldg(cw + i * NK + k);
            Wl[k] = __ldg(cw + (NLOD + i) * NK + k);
        }
        const float tcur = __ldg(tcu + i);
        const float tclr = __ldg(tcl + i);

        // register tables: fp32 diag (d=3) + bf16 pairs for d0 (j=i-3), d1 (j=i-2)
        float4 D[NK];
        uint4  R01[NK];
        {
            const int j0 = i - 3, j1 = i - 2;
            const bool v0 = (j0 >= 0), v1 = (j1 >= 0);
            #pragma unroll
            for (int k = 0; k < NK; k++) {
                long base = ((long)k * NLOD + i) * NLOD;
                D[k] = make_float4(__ldg(tm11 + base + i), __ldg(tm12 + base + i),
                                   __ldg(tm21 + base + i), __ldg(tm22 + base + i));
                float a11 = 0.f, a12 = 0.f, a21 = 0.f, a22 = 0.f;
                float c11 = 0.f, c12 = 0.f, c21 = 0.f, c22 = 0.f;
                if (v0) {
                    a11 = __ldg(tm11 + base + j0); a12 = __ldg(tm12 + base + j0);
                    a21 = __ldg(tm21 + base + j0); a22 = __ldg(tm22 + base + j0);
                }
                if (v1) {
                    c11 = __ldg(tm11 + base + j1); c12 = __ldg(tm12 + base + j1);
                    c21 = __ldg(tm21 + base + j1); c22 = __ldg(tm22 + base + j1);
                }
                R01[k] = make_uint4(pk(a11, a12), pk(a21, a22),
                                    pk(c11, c12), pk(c21, c22));
            }
        }

        // carry partial in registers (tc pre-subtracted; re-added at combine)
        float cmu = imean[(long)b * 2 * NLOD + i];
        float cml = imean[(long)b * 2 * NLOD + NLOD + i];
        float ccu = icu[(long)b * NLOD + i] - tcur;
        float ccl = icl[(long)b * NLOD + i] - tclr;
        float ccs = ics[(long)b * NLOD + i];
        float obs_r = __ldg(lobs  + ((long)b * NT) * NLOD + i);
        float ov_r  = __ldg(ovars + ((long)b * NT) * NLOD + i);

        for (int t = 0; t < NT; t++) {
            // ---- phase 1: combine h1 partial, obs update, logits ----
            float4 pp = p4h1[i];
            float  ps = p1h1[i];
            float pmU = cmu + pp.x;
            float pmL = cml + pp.y;
            float cU  = (ccu + pp.z) + tcur;
            float cL  = (ccl + pp.w) + tclr;
            float cS  = ccs + ps;

            float denom = cU + ov_r;
            float rd    = 1.0f / denom;
            float qu    = cU * rd;
            float ql    = cS * rd;
            float res   = obs_r - pmU;
            float pu    = pmU + qu * res;
            float pl    = pmL + ql * res;
            float cf    = 1.0f - qu;
            float pcu   = cf * cU;
            float pcl   = cL - ql * cS;
            float pcs   = cf * cS;

            if (t + 1 < NT) {
                obs_r = __ldg(lobs  + ((long)b * NT + t + 1) * NLOD + i);
                ov_r  = __ldg(ovars + ((long)b * NT + t + 1) * NLOD + i);
            }

            s_st[3 + i] = make_float4(pu, pl, pcu, pcl);
            s_cs[3 + i] = pcs;

            long obase = (long)b * NT + t;
            out_pm[obase * 2 * NLOD + i]        = pu;
            out_pm[obase * 2 * NLOD + NLOD + i] = pl;
            out_cu[obase * NLOD + i] = pcu;
            out_cl[obase * NLOD + i] = pcl;
            out_cs[obase * NLOD + i] = pcs;

            // logits over 128 rows (value-splitting butterfly)
            float v[NK];
            #pragma unroll
            for (int k = 0; k < NK; k++) v[k] = fmaf(pu, Wu[k], pl * Wl[k]);
            #pragma unroll
            for (int k = 0; k < NK; k++) v[k] += __shfl_xor_sync(0xffffffffu, v[k], 16);
            RED_ROUND(8)
            RED_ROUND(4)
            RED_ROUND(2)
            RED_ROUND(1)
            if (lane < 16) red[lane * 4 + warp] = v[0];
            bar256();   // B1

            // ---- phase 2: softmax + A-gen d{0,1,3} + matvec ----
            float aw;
            SOFTMAX_AW(aw)

            float D11 = 0.f, D12 = 0.f, D21 = 0.f, D22 = 0.f;
            unsigned long long P0 = 0ull, Q0 = 0ull, P1 = 0ull, Q1 = 0ull;
            #pragma unroll
            for (int k = 0; k < NK; k++) {
                float a = __shfl_sync(0xffffffffu, aw, k);
                unsigned long long a2 = dup2(a);
                uint4 r = R01[k];
                pair_fma(P0, r.x, a2);
                pair_fma(Q0, r.y, a2);
                pair_fma(P1, r.z, a2);
                pair_fma(Q1, r.w, a2);
                D11 = fmaf(a, D[k].x, D11);
                D12 = fmaf(a, D[k].y, D12);
                D21 = fmaf(a, D[k].z, D21);
                D22 = fmaf(a, D[k].w, D22);
            }
            float nmu = 0.f, nml = 0.f, ncu = 0.f, ncl = 0.f, ncs = 0.f;
            float a11, a12, a21, a22;
            unpk2(P0, a11, a12); unpk2(Q0, a21, a22);
            BAND_ACC(0, a11, a12, a21, a22)
            unpk2(P1, a11, a12); unpk2(Q1, a21, a22);
            BAND_ACC(1, a11, a12, a21, a22)
            BAND_ACC(3, D11 + 1.0f, D12, D21, D22 + 1.0f)

            cmu = nmu; cml = nml; ccu = ncu; ccl = ncl; ccs = ncs;
            bar256();   // B2
        }
    } else {
        // ================== h1: diagonals {2,4,5,6} ==================
        // d2: j=i-1, d4: j=i+1, d5: j=i+2, d6: j=i+3
        uint4 Ra[NK], Rb[NK];
        {
            const int j2 = i - 1, j4 = i + 1, j5 = i + 2, j6 = i + 3;
            const bool v2 = (j2 >= 0);
            const bool v4 = (j4 < NLOD), v5 = (j5 < NLOD), v6 = (j6 < NLOD);
            #pragma unroll
            for (int k = 0; k < NK; k++) {
                long base = ((long)k * NLOD + i) * NLOD;
                float a11 = 0.f, a12 = 0.f, a21 = 0.f, a22 = 0.f;
                float b11 = 0.f, b12 = 0.f, b21 = 0.f, b22 = 0.f;
                float c11 = 0.f, c12 = 0.f, c21 = 0.f, c22 = 0.f;
                float d11 = 0.f, d12 = 0.f, d21 = 0.f, d22 = 0.f;
                if (v2) {
                    a11 = __ldg(tm11 + base + j2); a12 = __ldg(tm12 + base + j2);
                    a21 = __ldg(tm21 + base + j2); a22 = __ldg(tm22 + base + j2);
                }
                if (v4) {
                    b11 = __ldg(tm11 + base + j4); b12 = __ldg(tm12 + base + j4);
                    b21 = __ldg(tm21 + base + j4); b22 = __ldg(tm22 + base + j4);
                }
                if (v5) {
                    c11 = __ldg(tm11 + base + j5); c12 = __ldg(tm12 + base + j5);
                    c21 = __ldg(tm21 + base + j5); c22 = __ldg(tm22 + base + j5);
                }
                if (v6) {
                    d11 = __ldg(tm11 + base + j6); d12 = __ldg(tm12 + base + j6);
                    d21 = __ldg(tm21 + base + j6); d22 = __ldg(tm22 + base + j6);
                }
                Ra[k] = make_uint4(pk(a11, a12), pk(a21, a22),
                                   pk(b11, b12), pk(b21, b22));
                Rb[k] = make_uint4(pk(c11, c12), pk(c21, c22),
                                   pk(d11, d12), pk(d21, d22));
            }
        }

        for (int t = 0; t < NT; t++) {
            bar256();   // B1

            float aw;
            SOFTMAX_AW(aw)

            unsigned long long P2 = 0ull, Q2 = 0ull, P4 = 0ull, Q4 = 0ull;
            unsigned long long P5 = 0ull, Q5 = 0ull, P6 = 0ull, Q6 = 0ull;
            #pragma unroll
            for (int k = 0; k < NK; k++) {
                unsigned long long a2 = dup2(__shfl_sync(0xffffffffu, aw, k));
                uint4 ra = Ra[k], rb = Rb[k];
                pair_fma(P2, ra.x, a2);
                pair_fma(Q2, ra.y, a2);
                pair_fma(P4, ra.z, a2);
                pair_fma(Q4, ra.w, a2);
                pair_fma(P5, rb.x, a2);
                pair_fma(Q5, rb.y, a2);
                pair_fma(P6, rb.z, a2);
                pair_fma(Q6, rb.w, a2);
            }
            float nmu = 0.f, nml = 0.f, ncu = 0.f, ncl = 0.f, ncs = 0.f;
            float a11, a12, a21, a22;
            unpk2(P2, a11, a12); unpk2(Q2, a21, a22);
            BAND_ACC(2, a11, a12, a21, a22)
            unpk2(P4, a11, a12); unpk2(Q4, a21, a22);
            BAND_ACC(4, a11, a12, a21, a22)
            unpk2(P5, a11, a12); unpk2(Q5, a21, a22);
            BAND_ACC(5, a11, a12, a21, a22)
            unpk2(P6, a11, a12); unpk2(Q6, a21, a22);
            BAND_ACC(6, a11, a12, a21, a22)

            p4h1[i] = make_float4(nmu, nml, ncu, ncl);
            p1h1[i] = ncs;
            bar256();   // B2
        }
    }
}

extern "C" void kernel_launch(void* const* d_in, const int* in_sizes, int n_in,
                              void* d_out, int out_size)
{
    (void)in_sizes; (void)n_in; (void)out_size;
    const float* lobs  = (const float*)d_in[0];
    const float* ovars = (const float*)d_in[1];
    const float* imean = (const float*)d_in[2];
    const float* icu   = (const float*)d_in[3];
    const float* icl   = (const float*)d_in[4];
    const float* ics   = (const float*)d_in[5];
    const float* tm11  = (const float*)d_in[6];
    const float* tm12  = (const float*)d_in[7];
    const float* tm21  = (const float*)d_in[8];
    const float* tm22  = (const float*)d_in[9];
    const float* cw    = (const float*)d_in[10];
    const float* cb    = (const float*)d_in[11];
    const float* tcu   = (const float*)d_in[12];
    const float* tcl   = (const float*)d_in[13];
    float* out = (float*)d_out;

    rkn_kernel<<<NB, 256>>>(lobs, ovars, imean, icu, icl, ics,
                            tm11, tm12, tm21, tm22,
                            cw, cb, tcu, tcl, out);
}